// round 2
// baseline (speedup 1.0000x reference)
#include <cuda_runtime.h>
#include <cstddef>

#define A_FOCAL 0.25f
#define SS_LOW  0.4f
#define SS_HIGH 0.5f
#define IOU_EPS 0.01f

#define TPB    256
#define MAXK   128
#define MAXB   8
#define MAXBLK 1024

// Fixed-slot partial sums (deterministic reduction; no device allocation).
__device__ float g_stc[MAXB * MAXBLK];
__device__ float g_str[MAXB * MAXBLK];
__device__ float g_cnt[MAXB * MAXBLK];

template <int KFIX>
__global__ __launch_bounds__(TPB)
void ainno_main_kernel(const float* __restrict__ ssp,      // (B, A, 6)
                       const float* __restrict__ anchors,  // (A, 4) xywh
                       const float* __restrict__ gtp,      // (B, K, 4) xywh
                       int A, int Kdyn)
{
    const int K = (KFIX > 0) ? KFIX : Kdyn;

    __shared__ float4 s_box[MAXK];   // gt xyxy
    __shared__ float  s_area[MAXK];  // gt area
    __shared__ float  s_red[3 * (TPB / 32)];

    const int b = blockIdx.y;
    const int t = threadIdx.x;

    // Precompute gt xyxy + area exactly as reference does (x2=x+w first).
    for (int k = t; k < K; k += TPB) {
        float4 g = reinterpret_cast<const float4*>(gtp)[(size_t)b * K + k];
        float gx2 = g.x + g.z;
        float gy2 = g.y + g.w;
        s_box[k]  = make_float4(g.x, g.y, gx2, gy2);
        s_area[k] = (gx2 - g.x) * (gy2 - g.y);
    }
    __syncthreads();

    const int a = blockIdx.x * TPB + t;

    float stc_term = 0.0f, str_term = 0.0f, cnt_term = 0.0f;

    if (a < A) {
        float4 an = reinterpret_cast<const float4*>(anchors)[a];
        const float ax1 = an.x, ay1 = an.y;
        const float ax2 = an.x + an.z;
        const float ay2 = an.y + an.w;
        const float areaA = (ax2 - ax1) * (ay2 - ay1);

        // ---- IoU argmax scan: rank by exact ratio via cross-multiplication ----
        float bestI, bestS;
        int   bestK = 0;
        {
            float4 g = s_box[0];
            float w = fmaxf(fminf(ax2, g.z) - fmaxf(ax1, g.x), 0.0f);
            float h = fmaxf(fminf(ay2, g.w) - fmaxf(ay1, g.y), 0.0f);
            bestI = w * h;
            bestS = areaA + s_area[0];
        }
        #pragma unroll
        for (int k = 1; k < K; k++) {
            float4 g = s_box[k];
            float w = fmaxf(fminf(ax2, g.z) - fmaxf(ax1, g.x), 0.0f);
            float h = fmaxf(fminf(ay2, g.w) - fmaxf(ay1, g.y), 0.0f);
            float inter = w * h;
            float S = areaA + s_area[k];
            // iou = inter/(S-inter) monotone in inter/S (unions > 0):
            // strict '>' keeps first index on exact ties (matches argmax).
            bool gtc = (inter * bestS) > (bestI * S);
            bestI = gtc ? inter : bestI;
            bestS = gtc ? S     : bestS;
            bestK = gtc ? k     : bestK;
        }

        const float u = bestS - bestI;            // union of best match
        const float score = bestI / u;            // one fp32 division per anchor

        const bool pos = (score >= SS_HIGH);
        const bool neg = (score <  SS_LOW);

        if (pos | neg) {
            const float* pr = ssp + ((size_t)b * A + a) * 6;
            float2 p01 = *reinterpret_cast<const float2*>(pr);
            float2 p23 = *reinterpret_cast<const float2*>(pr + 2);
            float  x   = pr[4];                   // logit

            // focal terms: p = sigmoid(x); ce_pos = log(1+e^{-x}); ce_neg = x + ce_pos
            float e  = __expf(-x);
            float p  = 1.0f / (1.0f + e);
            float ce_pos = __logf(1.0f + e);

            if (pos) {
                float omp = 1.0f - p;
                stc_term = A_FOCAL * ce_pos * (omp * omp);
                cnt_term = 1.0f;

                // element-wise IoU of proposal box vs matched gt box
                float px1 = p01.x, py1 = p01.y;
                float px2 = px1 + p23.x;
                float py2 = py1 + p23.y;
                float pa  = (px2 - px1) * (py2 - py1);
                float4 tb = s_box[bestK];
                float ta  = s_area[bestK];
                float ew = fmaxf(fminf(px2, tb.z) - fmaxf(px1, tb.x), 0.0f);
                float eh = fmaxf(fminf(py2, tb.w) - fmaxf(py1, tb.y), 0.0f);
                float ei = ew * eh;
                float eiou = ei / (pa + ta - ei);
                str_term = -__logf(eiou + IOU_EPS);
            } else {
                float ce_neg = x + ce_pos;
                stc_term = (1.0f - A_FOCAL) * ce_neg * (p * p);
            }
        }
    }

    // ---- block reduction (fixed tree -> deterministic) ----
    #pragma unroll
    for (int o = 16; o > 0; o >>= 1) {
        stc_term += __shfl_down_sync(0xffffffffu, stc_term, o);
        str_term += __shfl_down_sync(0xffffffffu, str_term, o);
        cnt_term += __shfl_down_sync(0xffffffffu, cnt_term, o);
    }
    const int warp = t >> 5;
    const int lane = t & 31;
    if (lane == 0) {
        s_red[warp]                 = stc_term;
        s_red[(TPB / 32) + warp]    = str_term;
        s_red[2 * (TPB / 32) + warp] = cnt_term;
    }
    __syncthreads();
    if (t == 0) {
        float sc = 0.0f, st = 0.0f, c = 0.0f;
        #pragma unroll
        for (int w = 0; w < TPB / 32; w++) {
            sc += s_red[w];
            st += s_red[(TPB / 32) + w];
            c  += s_red[2 * (TPB / 32) + w];
        }
        const int slot = b * MAXBLK + blockIdx.x;
        g_stc[slot] = sc;
        g_str[slot] = st;
        g_cnt[slot] = c;
    }
}

__global__ void ainno_finish_kernel(float* __restrict__ out, int B, int nblk)
{
    __shared__ float s_tot[MAXB];
    int b = threadIdx.x;
    if (b < B) {
        float sc = 0.0f, st = 0.0f, c = 0.0f;
        for (int i = 0; i < nblk; i++) {
            sc += g_stc[b * MAXBLK + i];
            st += g_str[b * MAXBLK + i];
            c  += g_cnt[b * MAXBLK + i];
        }
        float safe = (c > 0.0f) ? c : 1.0f;
        s_tot[b] = sc / safe + ((c > 0.0f) ? st / safe : 0.0f);
    }
    __syncthreads();
    if (b == 0) {
        float tot = 0.0f;
        for (int i = 0; i < B; i++) tot += s_tot[i];
        out[0] = tot / (float)B;
    }
}

extern "C" void kernel_launch(void* const* d_in, const int* in_sizes, int n_in,
                              void* d_out, int out_size)
{
    const float* ssp     = (const float*)d_in[0];  // (B, A, 6)
    const float* anchors = (const float*)d_in[1];  // (A, 4)
    const float* gtp     = (const float*)d_in[2];  // (B, K, 4)

    const int A = in_sizes[1] / 4;
    const int B = in_sizes[0] / (A * 6);
    const int K = in_sizes[2] / (B * 4);

    const int nblk = (A + TPB - 1) / TPB;

    dim3 grid(nblk, B);
    if (K == 64) {
        ainno_main_kernel<64><<<grid, TPB>>>(ssp, anchors, gtp, A, K);
    } else {
        ainno_main_kernel<0><<<grid, TPB>>>(ssp, anchors, gtp, A, K);
    }
    ainno_finish_kernel<<<1, 32>>>((float*)d_out, B, nblk);
}

// round 4
// speedup vs baseline: 1.5193x; 1.5193x over previous
#include <cuda_runtime.h>
#include <cstddef>

#define A_FOCAL 0.25f
#define SS_LOW  0.4f
#define SS_HIGH 0.5f
#define IOU_EPS 0.01f

#define TPB    256
#define APT    2            // anchors per thread
#define MAXK   128
#define MAXB   8
#define MAXBLK 1024

// Fixed-slot partial sums (deterministic reduction; no device allocation).
__device__ float g_stc[MAXB * MAXBLK];
__device__ float g_str[MAXB * MAXBLK];
__device__ float g_cnt[MAXB * MAXBLK];

struct Acc { float stc, str, cnt; };

// Per-anchor epilogue: focal + (-log elementwise-IoU) terms.
__device__ __forceinline__ void epilogue(const float* __restrict__ ssp,
                                         const float4* __restrict__ s_box,
                                         const float*  __restrict__ s_area,
                                         size_t base_off, int a,
                                         float bestI, float bestS, int bestK,
                                         Acc& acc)
{
    const float u     = bestS - bestI;
    const float score = bestI / u;          // one IEEE div per anchor

    const bool pos = (score >= SS_HIGH);
    const bool neg = (score <  SS_LOW);
    if (!(pos | neg)) return;

    const float* pr = ssp + (base_off + (size_t)a) * 6;
    float2 p01 = *reinterpret_cast<const float2*>(pr);
    float2 p23 = *reinterpret_cast<const float2*>(pr + 2);
    float  x   = pr[4];                     // logit

    float e  = __expf(-x);
    float p  = 1.0f / (1.0f + e);
    float ce_pos = __logf(1.0f + e);        // log(1+e^{-x})

    if (pos) {
        float omp = 1.0f - p;
        acc.stc += A_FOCAL * ce_pos * (omp * omp);
        acc.cnt += 1.0f;

        float px1 = p01.x, py1 = p01.y;
        float px2 = px1 + p23.x;
        float py2 = py1 + p23.y;
        float pa  = (px2 - px1) * (py2 - py1);
        float4 tb = s_box[bestK];
        float ta  = s_area[bestK];
        float ew = fmaxf(fminf(px2, tb.z) - fmaxf(px1, tb.x), 0.0f);
        float eh = fmaxf(fminf(py2, tb.w) - fmaxf(py1, tb.y), 0.0f);
        float ei = ew * eh;
        float eiou = ei / (pa + ta - ei);
        acc.str += -__logf(eiou + IOU_EPS);
    } else {
        float ce_neg = x + ce_pos;
        acc.stc += (1.0f - A_FOCAL) * ce_neg * (p * p);
    }
}

template <int KFIX>
__global__ __launch_bounds__(TPB)
void ainno_main_kernel(const float* __restrict__ ssp,      // (B, A, 6)
                       const float* __restrict__ anchors,  // (A, 4) xywh
                       const float* __restrict__ gtp,      // (B, K, 4) xywh
                       int A, int Kdyn)
{
    const int K = (KFIX > 0) ? KFIX : Kdyn;

    __shared__ float4 s_box[MAXK];   // gt xyxy
    __shared__ float  s_area[MAXK];  // gt area
    __shared__ float  s_red[3 * (TPB / 32)];

    const int b = blockIdx.y;
    const int t = threadIdx.x;

    // Precompute gt xyxy + area exactly as the reference (x2=x+w first).
    for (int k = t; k < K; k += TPB) {
        float4 g = reinterpret_cast<const float4*>(gtp)[(size_t)b * K + k];
        float gx2 = g.x + g.z;
        float gy2 = g.y + g.w;
        s_box[k]  = make_float4(g.x, g.y, gx2, gy2);
        s_area[k] = (gx2 - g.x) * (gy2 - g.y);
    }
    __syncthreads();

    const int a0 = blockIdx.x * (TPB * APT) + t;   // anchor 0
    const int a1 = a0 + TPB;                       // anchor 1
    const bool v0 = (a0 < A);
    const bool v1 = (a1 < A);

    // Load both anchor boxes (zeros if OOB; loop math is then harmless).
    float4 an0 = v0 ? reinterpret_cast<const float4*>(anchors)[a0]
                    : make_float4(0.f, 0.f, 0.f, 0.f);
    float4 an1 = v1 ? reinterpret_cast<const float4*>(anchors)[a1]
                    : make_float4(0.f, 0.f, 0.f, 0.f);

    const float ax1_0 = an0.x, ay1_0 = an0.y;
    const float ax2_0 = an0.x + an0.z, ay2_0 = an0.y + an0.w;
    const float areaA0 = (ax2_0 - ax1_0) * (ay2_0 - ay1_0);
    const float ax1_1 = an1.x, ay1_1 = an1.y;
    const float ax2_1 = an1.x + an1.z, ay2_1 = an1.y + an1.w;
    const float areaA1 = (ax2_1 - ax1_1) * (ay2_1 - ay1_1);

    // ---- IoU argmax scan for both anchors, one LDS pass ----
    // Rank by exact ratio via cross-multiplication:
    // iou = inter/(S-inter) is monotone in inter/S; strict '>' keeps the
    // first index on exact ties (matches jnp.argmax).
    float bI0, bS0, bI1, bS1;
    int   bK0 = 0, bK1 = 0;
    {
        float4 g = s_box[0];
        float Ag = s_area[0];
        float w0 = fmaxf(fminf(ax2_0, g.z) - fmaxf(ax1_0, g.x), 0.0f);
        float h0 = fmaxf(fminf(ay2_0, g.w) - fmaxf(ay1_0, g.y), 0.0f);
        bI0 = w0 * h0;  bS0 = areaA0 + Ag;
        float w1 = fmaxf(fminf(ax2_1, g.z) - fmaxf(ax1_1, g.x), 0.0f);
        float h1 = fmaxf(fminf(ay2_1, g.w) - fmaxf(ay1_1, g.y), 0.0f);
        bI1 = w1 * h1;  bS1 = areaA1 + Ag;
    }
    #pragma unroll
    for (int k = 1; k < K; k++) {
        float4 g = s_box[k];
        float Ag = s_area[k];

        float w0 = fmaxf(fminf(ax2_0, g.z) - fmaxf(ax1_0, g.x), 0.0f);
        float h0 = fmaxf(fminf(ay2_0, g.w) - fmaxf(ay1_0, g.y), 0.0f);
        float i0 = w0 * h0;
        float S0 = areaA0 + Ag;
        bool c0 = (i0 * bS0) > (bI0 * S0);
        bI0 = c0 ? i0 : bI0;  bS0 = c0 ? S0 : bS0;  bK0 = c0 ? k : bK0;

        float w1 = fmaxf(fminf(ax2_1, g.z) - fmaxf(ax1_1, g.x), 0.0f);
        float h1 = fmaxf(fminf(ay2_1, g.w) - fmaxf(ay1_1, g.y), 0.0f);
        float i1 = w1 * h1;
        float S1 = areaA1 + Ag;
        bool c1 = (i1 * bS1) > (bI1 * S1);
        bI1 = c1 ? i1 : bI1;  bS1 = c1 ? S1 : bS1;  bK1 = c1 ? k : bK1;
    }

    Acc acc = {0.0f, 0.0f, 0.0f};
    const size_t base_off = (size_t)b * A;
    if (v0) epilogue(ssp, s_box, s_area, base_off, a0, bI0, bS0, bK0, acc);
    if (v1) epilogue(ssp, s_box, s_area, base_off, a1, bI1, bS1, bK1, acc);

    // ---- block reduction (fixed tree -> deterministic) ----
    #pragma unroll
    for (int o = 16; o > 0; o >>= 1) {
        acc.stc += __shfl_down_sync(0xffffffffu, acc.stc, o);
        acc.str += __shfl_down_sync(0xffffffffu, acc.str, o);
        acc.cnt += __shfl_down_sync(0xffffffffu, acc.cnt, o);
    }
    const int warp = t >> 5;
    const int lane = t & 31;
    if (lane == 0) {
        s_red[warp]                  = acc.stc;
        s_red[(TPB / 32) + warp]     = acc.str;
        s_red[2 * (TPB / 32) + warp] = acc.cnt;
    }
    __syncthreads();
    if (t == 0) {
        float sc = 0.0f, st = 0.0f, c = 0.0f;
        #pragma unroll
        for (int w = 0; w < TPB / 32; w++) {
            sc += s_red[w];
            st += s_red[(TPB / 32) + w];
            c  += s_red[2 * (TPB / 32) + w];
        }
        const int slot = b * MAXBLK + blockIdx.x;
        g_stc[slot] = sc;
        g_str[slot] = st;
        g_cnt[slot] = c;
    }
}

// Parallel deterministic finish: 256 threads per batch, strided loads,
// fixed shuffle/shared reduction tree.
__global__ __launch_bounds__(1024)
void ainno_finish_kernel(float* __restrict__ out, int B, int nblk)
{
    __shared__ float s_w[3 * 32];
    __shared__ float s_bt[MAXB];

    const int t    = threadIdx.x;
    const int warp = t >> 5;
    const int lane = t & 31;

    for (int b0 = 0; b0 < B; b0 += 4) {
        const int b = b0 + (t >> 8);
        float sc = 0.0f, st = 0.0f, c = 0.0f;
        if (b < B) {
            for (int i = (t & 255); i < nblk; i += 256) {
                sc += g_stc[b * MAXBLK + i];
                st += g_str[b * MAXBLK + i];
                c  += g_cnt[b * MAXBLK + i];
            }
        }
        #pragma unroll
        for (int o = 16; o > 0; o >>= 1) {
            sc += __shfl_down_sync(0xffffffffu, sc, o);
            st += __shfl_down_sync(0xffffffffu, st, o);
            c  += __shfl_down_sync(0xffffffffu, c,  o);
        }
        if (lane == 0) {
            s_w[warp]      = sc;
            s_w[32 + warp] = st;
            s_w[64 + warp] = c;
        }
        __syncthreads();
        if ((t & 255) == 0 && b < B) {
            float SC = 0.0f, ST = 0.0f, C = 0.0f;
            const int w0 = warp;   // first of this batch's 8 warps
            #pragma unroll
            for (int w = 0; w < 8; w++) {
                SC += s_w[w0 + w];
                ST += s_w[32 + w0 + w];
                C  += s_w[64 + w0 + w];
            }
            float safe = (C > 0.0f) ? C : 1.0f;
            s_bt[b] = SC / safe + ((C > 0.0f) ? ST / safe : 0.0f);
        }
        __syncthreads();
    }

    if (t == 0) {
        float tot = 0.0f;
        for (int i = 0; i < B; i++) tot += s_bt[i];
        out[0] = tot / (float)B;
    }
}

extern "C" void kernel_launch(void* const* d_in, const int* in_sizes, int n_in,
                              void* d_out, int out_size)
{
    const float* ssp     = (const float*)d_in[0];  // (B, A, 6)
    const float* anchors = (const float*)d_in[1];  // (A, 4)
    const float* gtp     = (const float*)d_in[2];  // (B, K, 4)

    const int A = in_sizes[1] / 4;
    const int B = in_sizes[0] / (A * 6);
    const int K = in_sizes[2] / (B * 4);

    const int nblk = (A + TPB * APT - 1) / (TPB * APT);

    dim3 grid(nblk, B);
    if (K == 64) {
        ainno_main_kernel<64><<<grid, TPB>>>(ssp, anchors, gtp, A, K);
    } else {
        ainno_main_kernel<0><<<grid, TPB>>>(ssp, anchors, gtp, A, K);
    }
    ainno_finish_kernel<<<1, 1024>>>((float*)d_out, B, nblk);
}